// round 14
// baseline (speedup 1.0000x reference)
#include <cuda_runtime.h>
#include <cuda_bf16.h>
#include <cstdint>

#define FULLMASK 0xffffffffu
#define EMPTYV 3.402823466e38f

constexpr int Bc = 8, Nc = 16384, Fc = 32, Sc = 2048, Kc = 32, OUTc = 128;

// Scratch (device globals: allocation-free)
__device__ float g_xsq[Bc * Nc];
__device__ int   g_knn[Bc * Sc * Kc];

// ---------------------------------------------------------------------------
// Packed fp32x2 helpers
// ---------------------------------------------------------------------------
__device__ __forceinline__ unsigned long long splat2(float v) {
    unsigned long long r;
    asm("mov.b64 %0, {%1, %1};" : "=l"(r) : "r"(__float_as_uint(v)));
    return r;
}
__device__ __forceinline__ void fma2(unsigned long long& d,
                                     unsigned long long a,
                                     unsigned long long b) {
    asm("fma.rn.f32x2 %0, %1, %2, %0;" : "+l"(d) : "l"(a), "l"(b));
}
__device__ __forceinline__ float2 unpack2(unsigned long long v) {
    unsigned int lo, hi;
    asm("mov.b64 {%0, %1}, %2;" : "=r"(lo), "=r"(hi) : "l"(v));
    return make_float2(__uint_as_float(lo), __uint_as_float(hi));
}

// ---------------------------------------------------------------------------
// cp.async helpers
// ---------------------------------------------------------------------------
__device__ __forceinline__ void cpasync16(void* dst, const void* src) {
    uint32_t d = (uint32_t)__cvta_generic_to_shared(dst);
    asm volatile("cp.async.ca.shared.global [%0], [%1], 16;" :: "r"(d), "l"(src));
}
__device__ __forceinline__ void cpasync4(void* dst, const void* src) {
    uint32_t d = (uint32_t)__cvta_generic_to_shared(dst);
    asm volatile("cp.async.ca.shared.global [%0], [%1], 4;" :: "r"(d), "l"(src));
}
__device__ __forceinline__ void cpasync_commit() {
    asm volatile("cp.async.commit_group;");
}
__device__ __forceinline__ void cpasync_wait1() {
    asm volatile("cp.async.wait_group 1;" ::: "memory");
}

// ---------------------------------------------------------------------------
// Kernel 1: x_sq
// ---------------------------------------------------------------------------
__global__ void xsq_kernel(const float* __restrict__ x) {
    int i = blockIdx.x * blockDim.x + threadIdx.x;
    if (i >= Bc * Nc) return;
    const float4* p = (const float4*)(x + (size_t)i * Fc);
    float s = 0.f;
#pragma unroll
    for (int c = 0; c < 8; ++c) {
        float4 v = p[c];
        s += v.x * v.x + v.y * v.y + v.z * v.z + v.w * v.w;
    }
    g_xsq[i] = s;
}

// ---------------------------------------------------------------------------
// Kernel 2a/2b: sampled_batch output [B, F, S] (split so ncu's fixed skip
// lands on the knn kernel)
// ---------------------------------------------------------------------------
__global__ void sampled_kernel(const float* __restrict__ x,
                               const int* __restrict__ sidx,
                               float* __restrict__ out2, int base) {
    int i = base + blockIdx.x * blockDim.x + threadIdx.x;
    if (i >= Bc * Fc * Sc) return;
    int b = i / (Fc * Sc);
    int r = i - b * Fc * Sc;
    int f = r / Sc;
    int s = r - f * Sc;
    int row = sidx[b * Sc + s];
    out2[i] = x[((size_t)(b * Nc + row)) * Fc + f];
}

// ---------------------------------------------------------------------------
// Warp-level bitonic helpers
// ---------------------------------------------------------------------------
__device__ __forceinline__ void cmpSwap(float& d, int& i, int j, bool dirAsc, int lane) {
    float od = __shfl_xor_sync(FULLMASK, d, j);
    int   oi = __shfl_xor_sync(FULLMASK, i, j);
    bool lower = ((lane & j) == 0);
    bool less = (d < od) || (d == od && i < oi);
    bool keep = dirAsc ? (lower == less) : (lower != less);
    if (!keep) { d = od; i = oi; }
}

__device__ __forceinline__ void sortDesc32(float& d, int& i, int lane) {
#pragma unroll
    for (int k = 2; k <= 32; k <<= 1) {
#pragma unroll
        for (int j = k >> 1; j > 0; j >>= 1) {
            bool asc = ((lane & k) == 0);
            cmpSwap(d, i, j, !asc, lane);
        }
    }
}

__device__ __forceinline__ void mergeTop(float& cd, int& ci, float& bd, int& bi, int lane) {
    sortDesc32(bd, bi, lane);
    bool takeNew = (bd < cd) || (bd == cd && bi < ci);
    float nd = takeNew ? bd : cd;
    int   ni = takeNew ? bi : ci;
#pragma unroll
    for (int j = 16; j > 0; j >>= 1) cmpSwap(nd, ni, j, true, lane);
    cd = nd; ci = ni;
}

// ---------------------------------------------------------------------------
// Kernel 3: fused distance + top-K
// Block: 256 thr, 8 warps, 4 queries/warp -> 32 queries/block, 512 blocks.
// Small footprint: ~61KB smem + <=85 regs -> 3 blocks/SM (24 warps) for
// latency hiding (R12 profile showed occ 20.5%, issue 39% at 128 regs).
// ---------------------------------------------------------------------------
constexpr int QSTRIDE = 36;   // padded row stride (floats) for qt2
constexpr int CAPk = 64;      // overflow-list capacity per query

struct KnnSmem {
    float qt2[32 * QSTRIDE];            // [f][q] transposed, padded
    float sq_s[32];
    float xb[2][128 * 32];              // double-buffered swizzled tiles
    float xsq_s[2][128];
    float curD[8][4][32];               // running top-32 per (warp, query)
    int   curI[8][4][32];
    unsigned long long list[8][4][CAPk];
    int   cnt[8][4];
};
constexpr int SMEM_KNN = (int)sizeof(KnnSmem);

// merge list into curD/curI; returns new threshold (lane-31 value, all lanes)
__device__ __forceinline__ float reselect(KnnSmem* sm, int w, int qi, int lane) {
    float cd = sm->curD[w][qi][lane];
    int   ci = sm->curI[w][qi][lane];
    int n = sm->cnt[w][qi];
    for (int base = 0; base < n; base += 32) {
        float bd = EMPTYV; int bi = 0x7fffffff;
        if (base + lane < n) {
            unsigned long long e = sm->list[w][qi][base + lane];
            bd = __uint_as_float((unsigned)e);
            bi = (int)(unsigned)(e >> 32);
        }
        mergeTop(cd, ci, bd, bi, lane);
    }
    sm->curD[w][qi][lane] = cd;
    sm->curI[w][qi][lane] = ci;
    sm->cnt[w][qi] = 0;
    return __shfl_sync(FULLMASK, cd, 31);
}

// rare push path; returns (possibly refreshed) threshold
__device__ __noinline__ float pushSlow(KnnSmem* sm, int w, int qi, int lane,
                                       float thr, float d0, float d1, float d2,
                                       float d3, int nbase) {
#pragma unroll
    for (int s2 = 0; s2 < 4; ++s2) {
        float dv = (s2 == 0) ? d0 : (s2 == 1) ? d1 : (s2 == 2) ? d2 : d3;
        bool beat = dv < thr;
        unsigned bm = __ballot_sync(FULLMASK, beat);
        if (bm) {
            int c0 = sm->cnt[w][qi];
            if (beat) {
                int rank = __popc(bm & ((1u << lane) - 1));
                unsigned long long e =
                    ((unsigned long long)(unsigned)(nbase + s2 * 32 + lane) << 32)
                  | (unsigned long long)__float_as_uint(dv);
                sm->list[w][qi][c0 + rank] = e;
            }
            int c1 = c0 + __popc(bm);
            sm->cnt[w][qi] = c1;
            if (c1 >= 32) thr = reselect(sm, w, qi, lane);
        }
    }
    return thr;
}

__device__ __forceinline__ void loadTile(KnnSmem* sm, const float* __restrict__ x,
                                         int b, int tile, int buf, int tid) {
    int n0 = tile * 128;
#pragma unroll
    for (int it = 0; it < 4; ++it) {
        int t = tid + it * 256;
        int r = t >> 3, p = t & 7;
        int off = r * 128 + p * 16;
        off ^= (off >> 3) & 0x70;
        cpasync16((char*)sm->xb[buf] + off,
                  x + ((size_t)(b * Nc + n0 + r)) * Fc + p * 4);
    }
    if (tid < 128) cpasync4(&sm->xsq_s[buf][tid], &g_xsq[b * Nc + n0 + tid]);
}

__global__ __launch_bounds__(256, 3) void knn_kernel(const float* __restrict__ x,
                                                     const int* __restrict__ sidx) {
    extern __shared__ char smem_raw[];
    KnnSmem* sm = (KnnSmem*)smem_raw;

    int b = blockIdx.x >> 6;                 // 64 blocks per batch
    int qbase = (blockIdx.x & 63) * 32;
    int tid = threadIdx.x, lane = tid & 31, w = tid >> 5;
    int wq = w * 4;

    // init selection state
    if (tid < 32) sm->cnt[tid >> 2][tid & 3] = 0;
    for (int t = tid; t < 8 * 4 * 32; t += 256) {
        ((float*)sm->curD)[t] = EMPTYV;
        ((int*)sm->curI)[t] = 0;
    }

    // prologue: async-load tiles 0 and 1 as two commit groups
    loadTile(sm, x, b, 0, 0, tid);
    cpasync_commit();
    loadTile(sm, x, b, 1, 1, tid);
    cpasync_commit();

    // gather 32 queries into transposed qt2 + per-query sq (overlaps cp.async)
    {
        int q = tid >> 3, p = tid & 7;
        int row = sidx[b * Sc + qbase + q];
        float4 v = *(const float4*)(x + ((size_t)(b * Nc + row)) * Fc + p * 4);
        sm->qt2[(4 * p + 0) * QSTRIDE + q] = v.x;
        sm->qt2[(4 * p + 1) * QSTRIDE + q] = v.y;
        sm->qt2[(4 * p + 2) * QSTRIDE + q] = v.z;
        sm->qt2[(4 * p + 3) * QSTRIDE + q] = v.w;
        float part = v.x * v.x + v.y * v.y + v.z * v.z + v.w * v.w;
        part += __shfl_xor_sync(FULLMASK, part, 1);
        part += __shfl_xor_sync(FULLMASK, part, 2);
        part += __shfl_xor_sync(FULLMASK, part, 4);
        if (p == 0) sm->sq_s[q] = part;
    }
    __syncthreads();   // queries visible

    float sqv[4], tr[4];
#pragma unroll
    for (int qi = 0; qi < 4; ++qi) { sqv[qi] = sm->sq_s[wq + qi]; tr[qi] = EMPTYV; }

    for (int t = 0; t < 128; ++t) {
        int cur = t & 1;
        cpasync_wait1();       // tile t complete; tile t+1 may still be in flight
        __syncthreads();       // all warps see tile t; prior buffer reads done

        // ---- dot products on current tile
        const float* xbc = sm->xb[cur];
        unsigned long long acc2[2][4];
#pragma unroll
        for (int m = 0; m < 2; ++m)
#pragma unroll
            for (int s2 = 0; s2 < 4; ++s2) acc2[m][s2] = 0ULL;

#pragma unroll
        for (int p = 0; p < 8; ++p) {
            unsigned long long qp[4][2];
#pragma unroll
            for (int j = 0; j < 4; ++j) {
                ulonglong2 qa = *(const ulonglong2*)&sm->qt2[(4 * p + j) * QSTRIDE + wq];
                qp[j][0] = qa.x; qp[j][1] = qa.y;
            }
#pragma unroll
            for (int s2 = 0; s2 < 4; ++s2) {
                int c = s2 * 32 + lane;
                int off = c * 128 + p * 16;
                off ^= (off >> 3) & 0x70;
                float4 xv = *(const float4*)((const char*)xbc + off);
                const float xe[4] = {xv.x, xv.y, xv.z, xv.w};
#pragma unroll
                for (int j = 0; j < 4; ++j) {
                    unsigned long long xs = splat2(xe[j]);
#pragma unroll
                    for (int m = 0; m < 2; ++m) fma2(acc2[m][s2], qp[j][m], xs);
                }
            }
        }

        float xq[4];
#pragma unroll
        for (int s2 = 0; s2 < 4; ++s2) xq[s2] = sm->xsq_s[cur][s2 * 32 + lane];
        int nbase = t * 128;

        // ---- selection: 1 ballot per query steady-state
#pragma unroll
        for (int m = 0; m < 2; ++m) {
            float2 av0 = unpack2(acc2[m][0]);
            float2 av1 = unpack2(acc2[m][1]);
            float2 av2 = unpack2(acc2[m][2]);
            float2 av3 = unpack2(acc2[m][3]);
#pragma unroll
            for (int h = 0; h < 2; ++h) {
                int qi = 2 * m + h;
                float a0 = h ? av0.y : av0.x;
                float a1 = h ? av1.y : av1.x;
                float a2 = h ? av2.y : av2.x;
                float a3 = h ? av3.y : av3.x;
                float d0 = sqv[qi] + xq[0] - 2.f * a0;
                float d1 = sqv[qi] + xq[1] - 2.f * a1;
                float d2 = sqv[qi] + xq[2] - 2.f * a2;
                float d3 = sqv[qi] + xq[3] - 2.f * a3;
                float dmin = fminf(fminf(d0, d1), fminf(d2, d3));
                if (__ballot_sync(FULLMASK, dmin < tr[qi])) {
                    tr[qi] = pushSlow(sm, w, qi, lane, tr[qi],
                                      d0, d1, d2, d3, nbase);
                }
            }
        }
        __syncthreads();       // all warps done reading tile t (buffer cur)

        // prefetch tile t+2 into the buffer just freed; keeps group count even
        if (t + 2 < 128) loadTile(sm, x, b, t + 2, cur, tid);
        cpasync_commit();
    }

    // final flush + write neighbor indices
#pragma unroll 1
    for (int qi = 0; qi < 4; ++qi) {
        if (sm->cnt[w][qi] > 0) reselect(sm, w, qi, lane);
        g_knn[(b * Sc + qbase + wq + qi) * Kc + lane] = sm->curI[w][qi][lane];
    }
}

// ---------------------------------------------------------------------------
// Kernel 4: gather neighbors, 2-layer pointwise MLP, max-pool over K.
// (unchanged from R6 best)
// ---------------------------------------------------------------------------
constexpr int GT_STRIDE = 36;
struct MlpSmem {
    float4 W1i[32 * 32];
    float4 W2i[128 * 32];
    float4 b1i[32];
    float  gt[4][32][GT_STRIDE];
    float  hsm[16][128 * 8];
    float  red[4][4][128];
};
constexpr int SMEM_MLP = (int)sizeof(MlpSmem);

__global__ __launch_bounds__(512, 1) void mlp_kernel(const float* __restrict__ x,
                                                     const float* __restrict__ W1,
                                                     const float* __restrict__ b1,
                                                     const float* __restrict__ W2,
                                                     const float* __restrict__ b2,
                                                     float* __restrict__ feat) {
    extern __shared__ char smem_raw[];
    MlpSmem* sm = (MlpSmem*)smem_raw;

    int tid = threadIdx.x, lane = tid & 31, w = tid >> 5;
    int q = w >> 2, kb = (w & 3) * 8;

    for (int t = tid; t < 4096; t += 512) {
        int f = t >> 7, l = (t >> 2) & 31, j = t & 3;
        ((float*)&sm->W1i[f * 32 + l])[j] = W1[(l + 32 * j) * Fc + f];
    }
    for (int t = tid; t < 16384; t += 512) {
        int o = t >> 7, l = (t >> 2) & 31, j = t & 3;
        ((float*)&sm->W2i[o * 32 + l])[j] = W2[(l + 32 * j) * OUTc + o];
    }
    if (tid < 32)
        sm->b1i[tid] = make_float4(b1[tid], b1[tid + 32], b1[tid + 64], b1[tid + 96]);

    for (int grp = blockIdx.x; grp < (Bc * Sc) / 4; grp += gridDim.x) {
        __syncthreads();
#pragma unroll
        for (int it = 0; it < 2; ++it) {
            int idx = tid + it * 512;
            int q2 = idx >> 8, k = (idx >> 3) & 31, p = idx & 7;
            int qg = grp * 4 + q2;
            int bq = qg >> 11;
            int row = g_knn[qg * Kc + k];
            float4 v = *(const float4*)(x + ((size_t)(bq * Nc + row)) * Fc + p * 4);
            sm->gt[q2][4 * p + 0][k] = v.x;
            sm->gt[q2][4 * p + 1][k] = v.y;
            sm->gt[q2][4 * p + 2][k] = v.z;
            sm->gt[q2][4 * p + 3][k] = v.w;
        }
        __syncthreads();

        unsigned long long h2[4][4];
        {
            float4 bb = sm->b1i[lane];
            const float be[4] = {bb.x, bb.y, bb.z, bb.w};
#pragma unroll
            for (int c = 0; c < 4; ++c) {
                unsigned long long bs = splat2(be[c]);
#pragma unroll
                for (int j = 0; j < 4; ++j) h2[c][j] = bs;
            }
#pragma unroll
            for (int f = 0; f < 32; ++f) {
                ulonglong2 g0 = *(const ulonglong2*)&sm->gt[q][f][kb];
                ulonglong2 g1 = *(const ulonglong2*)&sm->gt[q][f][kb + 4];
                float4 w1 = sm->W1i[f * 32 + lane];
                const float we[4] = {w1.x, w1.y, w1.z, w1.w};
#pragma unroll
                for (int c = 0; c < 4; ++c) {
                    unsigned long long ws = splat2(we[c]);
                    fma2(h2[c][0], ws, g0.x);
                    fma2(h2[c][1], ws, g0.y);
                    fma2(h2[c][2], ws, g1.x);
                    fma2(h2[c][3], ws, g1.y);
                }
            }
        }
        float* hw = sm->hsm[w];
#pragma unroll
        for (int c = 0; c < 4; ++c) {
            float2 p0 = unpack2(h2[c][0]);
            float2 p1 = unpack2(h2[c][1]);
            float2 p2 = unpack2(h2[c][2]);
            float2 p3 = unpack2(h2[c][3]);
            float4 va = make_float4(fmaxf(p0.x, 0.f), fmaxf(p0.y, 0.f),
                                    fmaxf(p1.x, 0.f), fmaxf(p1.y, 0.f));
            float4 vb = make_float4(fmaxf(p2.x, 0.f), fmaxf(p2.y, 0.f),
                                    fmaxf(p3.x, 0.f), fmaxf(p3.y, 0.f));
            *(float4*)&hw[(lane + 32 * c) * 8]     = va;
            *(float4*)&hw[(lane + 32 * c) * 8 + 4] = vb;
        }
        __syncwarp();

        unsigned long long y2[4][4];
#pragma unroll
        for (int c = 0; c < 4; ++c)
#pragma unroll
            for (int j = 0; j < 4; ++j) y2[c][j] = 0ULL;
#pragma unroll 8
        for (int o = 0; o < 128; ++o) {
            ulonglong2 hp0 = *(const ulonglong2*)&hw[o * 8];
            ulonglong2 hp1 = *(const ulonglong2*)&hw[o * 8 + 4];
            float4 w2 = sm->W2i[o * 32 + lane];
            const float we[4] = {w2.x, w2.y, w2.z, w2.w};
#pragma unroll
            for (int c = 0; c < 4; ++c) {
                unsigned long long ws = splat2(we[c]);
                fma2(y2[c][0], ws, hp0.x);
                fma2(y2[c][1], ws, hp0.y);
                fma2(y2[c][2], ws, hp1.x);
                fma2(y2[c][3], ws, hp1.y);
            }
        }
#pragma unroll
        for (int c = 0; c < 4; ++c) {
            float2 a0 = unpack2(y2[c][0]);
            float2 a1 = unpack2(y2[c][1]);
            float2 a2 = unpack2(y2[c][2]);
            float2 a3 = unpack2(y2[c][3]);
            float m = fmaxf(fmaxf(fmaxf(a0.x, a0.y), fmaxf(a1.x, a1.y)),
                            fmaxf(fmaxf(a2.x, a2.y), fmaxf(a3.x, a3.y)));
            sm->red[q][w & 3][lane + 32 * c] = m;
        }
        __syncthreads();

        {
            int q2 = tid >> 7, o = tid & 127;
            float v = sm->red[q2][0][o];
#pragma unroll
            for (int ww = 1; ww < 4; ++ww) v = fmaxf(v, sm->red[q2][ww][o]);
            int qg = grp * 4 + q2;
            int bq = qg >> 11, s = qg & 2047;
            feat[((size_t)bq * OUTc + o) * Sc + s] = v + b2[o];
        }
    }
}

// ---------------------------------------------------------------------------
extern "C" void kernel_launch(void* const* d_in, const int* in_sizes, int n_in,
                              void* d_out, int out_size) {
    const float* x    = (const float*)d_in[0];
    const int*   sidx = (const int*)d_in[1];
    const float* W1   = (const float*)d_in[2];
    const float* b1   = (const float*)d_in[3];
    const float* W2   = (const float*)d_in[4];
    const float* b2   = (const float*)d_in[5];
    float* out  = (float*)d_out;
    float* feat = out;                                  // [B, OUT, S]
    float* samp = out + (size_t)Bc * OUTc * Sc;         // [B, F, S]

    constexpr int SHALF = (Bc * Fc * Sc) / 2;
    xsq_kernel<<<(Bc * Nc) / 256, 256>>>(x);
    sampled_kernel<<<SHALF / 256, 256>>>(x, sidx, samp, 0);
    sampled_kernel<<<SHALF / 256, 256>>>(x, sidx, samp, SHALF);

    cudaFuncSetAttribute(knn_kernel, cudaFuncAttributeMaxDynamicSharedMemorySize, SMEM_KNN);
    knn_kernel<<<(Bc * Sc) / 32, 256, SMEM_KNN>>>(x, sidx);

    cudaFuncSetAttribute(mlp_kernel, cudaFuncAttributeMaxDynamicSharedMemorySize, SMEM_MLP);
    mlp_kernel<<<148, 512, SMEM_MLP>>>(x, W1, b1, W2, b2, feat);
}

// round 16
// speedup vs baseline: 1.0454x; 1.0454x over previous
#include <cuda_runtime.h>
#include <cuda_bf16.h>
#include <cstdint>

#define FULLMASK 0xffffffffu
#define EMPTYV 3.402823466e38f

constexpr int Bc = 8, Nc = 16384, Fc = 32, Sc = 2048, Kc = 32, OUTc = 128;

// Scratch (device globals: allocation-free)
__device__ float g_xsq[Bc * Nc];
__device__ int   g_knn[Bc * Sc * Kc];

// ---------------------------------------------------------------------------
// Packed fp32x2 helpers
// ---------------------------------------------------------------------------
__device__ __forceinline__ unsigned long long splat2(float v) {
    unsigned long long r;
    asm("mov.b64 %0, {%1, %1};" : "=l"(r) : "r"(__float_as_uint(v)));
    return r;
}
__device__ __forceinline__ void fma2(unsigned long long& d,
                                     unsigned long long a,
                                     unsigned long long b) {
    asm("fma.rn.f32x2 %0, %1, %2, %0;" : "+l"(d) : "l"(a), "l"(b));
}
__device__ __forceinline__ float2 unpack2(unsigned long long v) {
    unsigned int lo, hi;
    asm("mov.b64 {%0, %1}, %2;" : "=r"(lo), "=r"(hi) : "l"(v));
    return make_float2(__uint_as_float(lo), __uint_as_float(hi));
}

// ---------------------------------------------------------------------------
// cp.async helpers
// ---------------------------------------------------------------------------
__device__ __forceinline__ void cpasync16(void* dst, const void* src) {
    uint32_t d = (uint32_t)__cvta_generic_to_shared(dst);
    asm volatile("cp.async.ca.shared.global [%0], [%1], 16;" :: "r"(d), "l"(src));
}
__device__ __forceinline__ void cpasync4(void* dst, const void* src) {
    uint32_t d = (uint32_t)__cvta_generic_to_shared(dst);
    asm volatile("cp.async.ca.shared.global [%0], [%1], 4;" :: "r"(d), "l"(src));
}
__device__ __forceinline__ void cpasync_commit() {
    asm volatile("cp.async.commit_group;");
}
__device__ __forceinline__ void cpasync_wait1() {
    asm volatile("cp.async.wait_group 1;" ::: "memory");
}

// ---------------------------------------------------------------------------
// Kernel 1: x_sq
// ---------------------------------------------------------------------------
__global__ void xsq_kernel(const float* __restrict__ x) {
    int i = blockIdx.x * blockDim.x + threadIdx.x;
    if (i >= Bc * Nc) return;
    const float4* p = (const float4*)(x + (size_t)i * Fc);
    float s = 0.f;
#pragma unroll
    for (int c = 0; c < 8; ++c) {
        float4 v = p[c];
        s += v.x * v.x + v.y * v.y + v.z * v.z + v.w * v.w;
    }
    g_xsq[i] = s;
}

// ---------------------------------------------------------------------------
// Kernel 2a/2b: sampled_batch output [B, F, S] (split so ncu's fixed skip
// lands on the knn kernel)
// ---------------------------------------------------------------------------
__global__ void sampled_kernel(const float* __restrict__ x,
                               const int* __restrict__ sidx,
                               float* __restrict__ out2, int base) {
    int i = base + blockIdx.x * blockDim.x + threadIdx.x;
    if (i >= Bc * Fc * Sc) return;
    int b = i / (Fc * Sc);
    int r = i - b * Fc * Sc;
    int f = r / Sc;
    int s = r - f * Sc;
    int row = sidx[b * Sc + s];
    out2[i] = x[((size_t)(b * Nc + row)) * Fc + f];
}

// ---------------------------------------------------------------------------
// Warp-level bitonic helpers
// ---------------------------------------------------------------------------
__device__ __forceinline__ void cmpSwap(float& d, int& i, int j, bool dirAsc, int lane) {
    float od = __shfl_xor_sync(FULLMASK, d, j);
    int   oi = __shfl_xor_sync(FULLMASK, i, j);
    bool lower = ((lane & j) == 0);
    bool less = (d < od) || (d == od && i < oi);
    bool keep = dirAsc ? (lower == less) : (lower != less);
    if (!keep) { d = od; i = oi; }
}

__device__ __forceinline__ void sortDesc32(float& d, int& i, int lane) {
#pragma unroll
    for (int k = 2; k <= 32; k <<= 1) {
#pragma unroll
        for (int j = k >> 1; j > 0; j >>= 1) {
            bool asc = ((lane & k) == 0);
            cmpSwap(d, i, j, !asc, lane);
        }
    }
}

__device__ __forceinline__ void mergeTop(float& cd, int& ci, float& bd, int& bi, int lane) {
    sortDesc32(bd, bi, lane);
    bool takeNew = (bd < cd) || (bd == cd && bi < ci);
    float nd = takeNew ? bd : cd;
    int   ni = takeNew ? bi : ci;
#pragma unroll
    for (int j = 16; j > 0; j >>= 1) cmpSwap(nd, ni, j, true, lane);
    cd = nd; ci = ni;
}

// ---------------------------------------------------------------------------
// Kernel 3: fused distance + top-K
// Block: 256 thr, 8 warps, 8 queries/warp, 64 queries/block, 256 blocks.
// Pooled merge phase (balanced across warps) + padded-linear tile layout
// (36-float row stride: conflict-free, immediate-offset LDS, no swizzle ALU).
// ---------------------------------------------------------------------------
constexpr int QSTRIDE = 68;   // padded row stride (floats) for qt2
constexpr int XSTRIDE = 36;   // padded candidate-row stride (36 % 32 banks = 4)
constexpr int CAPk = 96;      // overflow-list capacity per query

struct KnnSmem {
    float qt2[32 * QSTRIDE];            // [f][q] transposed, padded
    float sq_s[64];
    float xb[2][128 * XSTRIDE];         // double-buffered padded tiles
    float xsq_s[2][128];
    float curD[8][8][32];               // running top-32 per (warp, query)
    int   curI[8][8][32];
    unsigned long long list[8][8][CAPk];
    int   cnt[8][8];
    float thr[8][8];                    // current 32nd-best per list
};
constexpr int SMEM_KNN = (int)sizeof(KnnSmem);

// merge list (wl,qi) into its curD/curI; updates smem thr; any warp may run it
__device__ __forceinline__ float reselect(KnnSmem* sm, int wl, int qi, int lane) {
    float cd = sm->curD[wl][qi][lane];
    int   ci = sm->curI[wl][qi][lane];
    int n = sm->cnt[wl][qi];
    for (int base = 0; base < n; base += 32) {
        float bd = EMPTYV; int bi = 0x7fffffff;
        if (base + lane < n) {
            unsigned long long e = sm->list[wl][qi][base + lane];
            bd = __uint_as_float((unsigned)e);
            bi = (int)(unsigned)(e >> 32);
        }
        mergeTop(cd, ci, bd, bi, lane);
    }
    sm->curD[wl][qi][lane] = cd;
    sm->curI[wl][qi][lane] = ci;
    sm->cnt[wl][qi] = 0;
    float t = __shfl_sync(FULLMASK, cd, 31);
    if (lane == 0) sm->thr[wl][qi] = t;
    return t;
}

// push path; emergency inline merge only at cnt>=64 (pooled phase handles rest)
__device__ __noinline__ float pushSlow(KnnSmem* sm, int w, int qi, int lane,
                                       float thr, float d0, float d1, float d2,
                                       float d3, int nbase) {
#pragma unroll
    for (int s2 = 0; s2 < 4; ++s2) {
        float dv = (s2 == 0) ? d0 : (s2 == 1) ? d1 : (s2 == 2) ? d2 : d3;
        bool beat = dv < thr;
        unsigned bm = __ballot_sync(FULLMASK, beat);
        if (bm) {
            int c0 = sm->cnt[w][qi];
            if (beat) {
                int rank = __popc(bm & ((1u << lane) - 1));
                unsigned long long e =
                    ((unsigned long long)(unsigned)(nbase + s2 * 32 + lane) << 32)
                  | (unsigned long long)__float_as_uint(dv);
                sm->list[w][qi][c0 + rank] = e;
            }
            int c1 = c0 + __popc(bm);
            sm->cnt[w][qi] = c1;
            if (c1 >= 64) thr = reselect(sm, w, qi, lane);   // emergency only
        }
    }
    return thr;
}

__device__ __forceinline__ void loadTile(KnnSmem* sm, const float* __restrict__ x,
                                         int b, int tile, int buf, int tid) {
    int n0 = tile * 128;
#pragma unroll
    for (int it = 0; it < 4; ++it) {
        int t = tid + it * 256;
        int r = t >> 3, p = t & 7;
        cpasync16((char*)sm->xb[buf] + r * (XSTRIDE * 4) + p * 16,
                  x + ((size_t)(b * Nc + n0 + r)) * Fc + p * 4);
    }
    if (tid < 128) cpasync4(&sm->xsq_s[buf][tid], &g_xsq[b * Nc + n0 + tid]);
}

__global__ __launch_bounds__(256, 2) void knn_kernel(const float* __restrict__ x,
                                                     const int* __restrict__ sidx) {
    extern __shared__ char smem_raw[];
    KnnSmem* sm = (KnnSmem*)smem_raw;

    int b = blockIdx.x >> 5;                 // 32 blocks per batch
    int qbase = (blockIdx.x & 31) * 64;
    int tid = threadIdx.x, lane = tid & 31, w = tid >> 5;
    int wq = w * 8;

    // init selection state
    if (tid < 64) {
        sm->cnt[tid >> 3][tid & 7] = 0;
        sm->thr[tid >> 3][tid & 7] = EMPTYV;
    }
    for (int t = tid; t < 8 * 8 * 32; t += 256) {
        ((float*)sm->curD)[t] = EMPTYV;
        ((int*)sm->curI)[t] = 0;
    }

    // prologue: async-load tiles 0 and 1 as two commit groups
    loadTile(sm, x, b, 0, 0, tid);
    cpasync_commit();
    loadTile(sm, x, b, 1, 1, tid);
    cpasync_commit();

    // gather 64 queries into transposed qt2 + per-query sq (overlaps cp.async)
#pragma unroll
    for (int it = 0; it < 2; ++it) {
        int idx = tid + it * 256;
        int q = idx >> 3, p = idx & 7;
        int row = sidx[b * Sc + qbase + q];
        float4 v = *(const float4*)(x + ((size_t)(b * Nc + row)) * Fc + p * 4);
        sm->qt2[(4 * p + 0) * QSTRIDE + q] = v.x;
        sm->qt2[(4 * p + 1) * QSTRIDE + q] = v.y;
        sm->qt2[(4 * p + 2) * QSTRIDE + q] = v.z;
        sm->qt2[(4 * p + 3) * QSTRIDE + q] = v.w;
        float part = v.x * v.x + v.y * v.y + v.z * v.z + v.w * v.w;
        part += __shfl_xor_sync(FULLMASK, part, 1);
        part += __shfl_xor_sync(FULLMASK, part, 2);
        part += __shfl_xor_sync(FULLMASK, part, 4);
        if (p == 0) sm->sq_s[q] = part;
    }
    __syncthreads();   // queries + init visible

    float sqv[8];
#pragma unroll
    for (int qi = 0; qi < 8; ++qi) sqv[qi] = sm->sq_s[wq + qi];

    for (int t = 0; t < 128; ++t) {
        int cur = t & 1;
        cpasync_wait1();       // tile t complete; tile t+1 may still be in flight
        __syncthreads();       // tile visible; prior merge-phase writes visible

        // per-tile threshold snapshot (stale-high is safe)
        float tr[8];
#pragma unroll
        for (int qi = 0; qi < 8; ++qi) tr[qi] = sm->thr[w][qi];

        // ---- dot products on current tile (immediate-offset LDS, no swizzle)
        const char* xr = (const char*)sm->xb[cur] + lane * (XSTRIDE * 4);
        unsigned long long acc2[4][4];
#pragma unroll
        for (int m = 0; m < 4; ++m)
#pragma unroll
            for (int s2 = 0; s2 < 4; ++s2) acc2[m][s2] = 0ULL;

#pragma unroll
        for (int p = 0; p < 8; ++p) {
            unsigned long long qp[4][4];
#pragma unroll
            for (int j = 0; j < 4; ++j) {
                ulonglong2 qa = *(const ulonglong2*)&sm->qt2[(4 * p + j) * QSTRIDE + wq];
                ulonglong2 qb = *(const ulonglong2*)&sm->qt2[(4 * p + j) * QSTRIDE + wq + 4];
                qp[j][0] = qa.x; qp[j][1] = qa.y;
                qp[j][2] = qb.x; qp[j][3] = qb.y;
            }
#pragma unroll
            for (int s2 = 0; s2 < 4; ++s2) {
                float4 xv = *(const float4*)(xr + s2 * (32 * XSTRIDE * 4) + p * 16);
                const float xe[4] = {xv.x, xv.y, xv.z, xv.w};
#pragma unroll
                for (int j = 0; j < 4; ++j) {
                    unsigned long long xs = splat2(xe[j]);
#pragma unroll
                    for (int m = 0; m < 4; ++m) fma2(acc2[m][s2], qp[j][m], xs);
                }
            }
        }

        float xq[4];
#pragma unroll
        for (int s2 = 0; s2 < 4; ++s2) xq[s2] = sm->xsq_s[cur][s2 * 32 + lane];
        int nbase = t * 128;

        // ---- selection: 1 ballot per query steady-state
#pragma unroll
        for (int m = 0; m < 4; ++m) {
            float2 av0 = unpack2(acc2[m][0]);
            float2 av1 = unpack2(acc2[m][1]);
            float2 av2 = unpack2(acc2[m][2]);
            float2 av3 = unpack2(acc2[m][3]);
#pragma unroll
            for (int h = 0; h < 2; ++h) {
                int qi = 2 * m + h;
                float a0 = h ? av0.y : av0.x;
                float a1 = h ? av1.y : av1.x;
                float a2 = h ? av2.y : av2.x;
                float a3 = h ? av3.y : av3.x;
                float d0 = sqv[qi] + xq[0] - 2.f * a0;
                float d1 = sqv[qi] + xq[1] - 2.f * a1;
                float d2 = sqv[qi] + xq[2] - 2.f * a2;
                float d3 = sqv[qi] + xq[3] - 2.f * a3;
                float dmin = fminf(fminf(d0, d1), fminf(d2, d3));
                if (__ballot_sync(FULLMASK, dmin < tr[qi])) {
                    tr[qi] = pushSlow(sm, w, qi, lane, tr[qi],
                                      d0, d1, d2, d3, nbase);
                }
            }
        }
        __syncthreads();       // lists stable; tile t reads done (buffer cur free)

        // prefetch tile t+2 into the freed buffer (overlaps merge phase)
        if (t + 2 < 128) loadTile(sm, x, b, t + 2, cur, tid);
        cpasync_commit();

        // ---- pooled merge phase: warp w services query-slot w of all warps
#pragma unroll 1
        for (int j = 0; j < 8; ++j) {
            if (sm->cnt[j][w] >= 32) reselect(sm, j, w, lane);
        }
        // next iteration's top __syncthreads orders these writes
    }
    __syncthreads();

    // final flush + writeback, same assignment (warp w owns lists (j, w))
#pragma unroll 1
    for (int j = 0; j < 8; ++j) {
        if (sm->cnt[j][w] > 0) reselect(sm, j, w, lane);
        g_knn[(b * Sc + qbase + j * 8 + w) * Kc + lane] = sm->curI[j][w][lane];
    }
}

// ---------------------------------------------------------------------------
// Kernel 4: gather neighbors, 2-layer pointwise MLP, max-pool over K.
// (unchanged from R6 best)
// ---------------------------------------------------------------------------
constexpr int GT_STRIDE = 36;
struct MlpSmem {
    float4 W1i[32 * 32];
    float4 W2i[128 * 32];
    float4 b1i[32];
    float  gt[4][32][GT_STRIDE];
    float  hsm[16][128 * 8];
    float  red[4][4][128];
};
constexpr int SMEM_MLP = (int)sizeof(MlpSmem);

__global__ __launch_bounds__(512, 1) void mlp_kernel(const float* __restrict__ x,
                                                     const float* __restrict__ W1,
                                                     const float* __restrict__ b1,
                                                     const float* __restrict__ W2,
                                                     const float* __restrict__ b2,
                                                     float* __restrict__ feat) {
    extern __shared__ char smem_raw[];
    MlpSmem* sm = (MlpSmem*)smem_raw;

    int tid = threadIdx.x, lane = tid & 31, w = tid >> 5;
    int q = w >> 2, kb = (w & 3) * 8;

    for (int t = tid; t < 4096; t += 512) {
        int f = t >> 7, l = (t >> 2) & 31, j = t & 3;
        ((float*)&sm->W1i[f * 32 + l])[j] = W1[(l + 32 * j) * Fc + f];
    }
    for (int t = tid; t < 16384; t += 512) {
        int o = t >> 7, l = (t >> 2) & 31, j = t & 3;
        ((float*)&sm->W2i[o * 32 + l])[j] = W2[(l + 32 * j) * OUTc + o];
    }
    if (tid < 32)
        sm->b1i[tid] = make_float4(b1[tid], b1[tid + 32], b1[tid + 64], b1[tid + 96]);

    for (int grp = blockIdx.x; grp < (Bc * Sc) / 4; grp += gridDim.x) {
        __syncthreads();
#pragma unroll
        for (int it = 0; it < 2; ++it) {
            int idx = tid + it * 512;
            int q2 = idx >> 8, k = (idx >> 3) & 31, p = idx & 7;
            int qg = grp * 4 + q2;
            int bq = qg >> 11;
            int row = g_knn[qg * Kc + k];
            float4 v = *(const float4*)(x + ((size_t)(bq * Nc + row)) * Fc + p * 4);
            sm->gt[q2][4 * p + 0][k] = v.x;
            sm->gt[q2][4 * p + 1][k] = v.y;
            sm->gt[q2][4 * p + 2][k] = v.z;
            sm->gt[q2][4 * p + 3][k] = v.w;
        }
        __syncthreads();

        unsigned long long h2[4][4];
        {
            float4 bb = sm->b1i[lane];
            const float be[4] = {bb.x, bb.y, bb.z, bb.w};
#pragma unroll
            for (int c = 0; c < 4; ++c) {
                unsigned long long bs = splat2(be[c]);
#pragma unroll
                for (int j = 0; j < 4; ++j) h2[c][j] = bs;
            }
#pragma unroll
            for (int f = 0; f < 32; ++f) {
                ulonglong2 g0 = *(const ulonglong2*)&sm->gt[q][f][kb];
                ulonglong2 g1 = *(const ulonglong2*)&sm->gt[q][f][kb + 4];
                float4 w1 = sm->W1i[f * 32 + lane];
                const float we[4] = {w1.x, w1.y, w1.z, w1.w};
#pragma unroll
                for (int c = 0; c < 4; ++c) {
                    unsigned long long ws = splat2(we[c]);
                    fma2(h2[c][0], ws, g0.x);
                    fma2(h2[c][1], ws, g0.y);
                    fma2(h2[c][2], ws, g1.x);
                    fma2(h2[c][3], ws, g1.y);
                }
            }
        }
        float* hw = sm->hsm[w];
#pragma unroll
        for (int c = 0; c < 4; ++c) {
            float2 p0 = unpack2(h2[c][0]);
            float2 p1 = unpack2(h2[c][1]);
            float2 p2 = unpack2(h2[c][2]);
            float2 p3 = unpack2(h2[c][3]);
            float4 va = make_float4(fmaxf(p0.x, 0.f), fmaxf(p0.y, 0.f),
                                    fmaxf(p1.x, 0.f), fmaxf(p1.y, 0.f));
            float4 vb = make_float4(fmaxf(p2.x, 0.f), fmaxf(p2.y, 0.f),
                                    fmaxf(p3.x, 0.f), fmaxf(p3.y, 0.f));
            *(float4*)&hw[(lane + 32 * c) * 8]     = va;
            *(float4*)&hw[(lane + 32 * c) * 8 + 4] = vb;
        }
        __syncwarp();

        unsigned long long y2[4][4];
#pragma unroll
        for (int c = 0; c < 4; ++c)
#pragma unroll
            for (int j = 0; j < 4; ++j) y2[c][j] = 0ULL;
#pragma unroll 8
        for (int o = 0; o < 128; ++o) {
            ulonglong2 hp0 = *(const ulonglong2*)&hw[o * 8];
            ulonglong2 hp1 = *(const ulonglong2*)&hw[o * 8 + 4];
            float4 w2 = sm->W2i[o * 32 + lane];
            const float we[4] = {w2.x, w2.y, w2.z, w2.w};
#pragma unroll
            for (int c = 0; c < 4; ++c) {
                unsigned long long ws = splat2(we[c]);
                fma2(y2[c][0], ws, hp0.x);
                fma2(y2[c][1], ws, hp0.y);
                fma2(y2[c][2], ws, hp1.x);
                fma2(y2[c][3], ws, hp1.y);
            }
        }
#pragma unroll
        for (int c = 0; c < 4; ++c) {
            float2 a0 = unpack2(y2[c][0]);
            float2 a1 = unpack2(y2[c][1]);
            float2 a2 = unpack2(y2[c][2]);
            float2 a3 = unpack2(y2[c][3]);
            float m = fmaxf(fmaxf(fmaxf(a0.x, a0.y), fmaxf(a1.x, a1.y)),
                            fmaxf(fmaxf(a2.x, a2.y), fmaxf(a3.x, a3.y)));
            sm->red[q][w & 3][lane + 32 * c] = m;
        }
        __syncthreads();

        {
            int q2 = tid >> 7, o = tid & 127;
            float v = sm->red[q2][0][o];
#pragma unroll
            for (int ww = 1; ww < 4; ++ww) v = fmaxf(v, sm->red[q2][ww][o]);
            int qg = grp * 4 + q2;
            int bq = qg >> 11, s = qg & 2047;
            feat[((size_t)bq * OUTc + o) * Sc + s] = v + b2[o];
        }
    }
}

// ---------------------------------------------------------------------------
extern "C" void kernel_launch(void* const* d_in, const int* in_sizes, int n_in,
                              void* d_out, int out_size) {
    const float* x    = (const float*)d_in[0];
    const int*   sidx = (const int*)d_in[1];
    const float* W1   = (const float*)d_in[2];
    const float* b1   = (const float*)d_in[3];
    const float* W2   = (const float*)d_in[4];
    const float* b2   = (const float*)d_in[5];
    float* out  = (float*)d_out;
    float* feat = out;                                  // [B, OUT, S]
    float* samp = out + (size_t)Bc * OUTc * Sc;         // [B, F, S]

    constexpr int SHALF = (Bc * Fc * Sc) / 2;
    xsq_kernel<<<(Bc * Nc) / 256, 256>>>(x);
    sampled_kernel<<<SHALF / 256, 256>>>(x, sidx, samp, 0);
    sampled_kernel<<<SHALF / 256, 256>>>(x, sidx, samp, SHALF);

    cudaFuncSetAttribute(knn_kernel, cudaFuncAttributeMaxDynamicSharedMemorySize, SMEM_KNN);
    knn_kernel<<<(Bc * Sc) / 64, 256, SMEM_KNN>>>(x, sidx);

    cudaFuncSetAttribute(mlp_kernel, cudaFuncAttributeMaxDynamicSharedMemorySize, SMEM_MLP);
    mlp_kernel<<<148, 512, SMEM_MLP>>>(x, W1, b1, W2, b2, feat);
}